// round 9
// baseline (speedup 1.0000x reference)
#include <cuda_runtime.h>

#define T_TOK 4096
#define D_DIM 2048
#define N_EXP 64
#define TOPK  2
#define CAP   160
#define TEC   (T_TOK * N_EXP * CAP)   // 41,943,040

// scratch (device globals; no allocation allowed)
__device__ int   g_te[T_TOK * TOPK];
__device__ float g_tw[T_TOK * TOPK];

#define BT 32
#define BK 32
#define GEMM_BLOCKS (T_TOK / BT)   // 128
#define XPAD 34
#define WPAD 68

// ---------------- Kernel A: GEMM + top2 + softmax ---------------------------
__global__ void __launch_bounds__(256) gemm_kernel(
    const float* __restrict__ x, const float* __restrict__ wg)
{
    __shared__ __align__(16) float sm[BK * XPAD + BK * WPAD];
    float* xsT = sm;                  // [BK][XPAD]
    float* wsT = sm + BK * XPAD;      // [BK][WPAD]

    int tid = threadIdx.x;
    int tx  = tid & 15;
    int ty  = tid >> 4;
    int tok0 = blockIdx.x * BT;

    float acc[2][4];
#pragma unroll
    for (int i = 0; i < 2; i++)
#pragma unroll
        for (int j = 0; j < 4; j++) acc[i][j] = 0.f;

    int xrow = tid >> 3;
    int c4   = tid & 7;

    for (int d0 = 0; d0 < D_DIM; d0 += BK) {
        float4 xv  = *(const float4*)&x [(size_t)(tok0 + xrow) * D_DIM + d0 + 4 * c4];
        float4 wv0 = *(const float4*)&wg[(size_t)(tid >> 3)        * D_DIM + d0 + 4 * c4];
        float4 wv1 = *(const float4*)&wg[(size_t)((tid >> 3) + 32) * D_DIM + d0 + 4 * c4];

        __syncthreads();
        xsT[(4 * c4 + 0) * XPAD + xrow] = xv.x;
        xsT[(4 * c4 + 1) * XPAD + xrow] = xv.y;
        xsT[(4 * c4 + 2) * XPAD + xrow] = xv.z;
        xsT[(4 * c4 + 3) * XPAD + xrow] = xv.w;
        int e0r = tid >> 3;
        wsT[(4 * c4 + 0) * WPAD + e0r] = wv0.x;
        wsT[(4 * c4 + 1) * WPAD + e0r] = wv0.y;
        wsT[(4 * c4 + 2) * WPAD + e0r] = wv0.z;
        wsT[(4 * c4 + 3) * WPAD + e0r] = wv0.w;
        wsT[(4 * c4 + 0) * WPAD + e0r + 32] = wv1.x;
        wsT[(4 * c4 + 1) * WPAD + e0r + 32] = wv1.y;
        wsT[(4 * c4 + 2) * WPAD + e0r + 32] = wv1.z;
        wsT[(4 * c4 + 3) * WPAD + e0r + 32] = wv1.w;
        __syncthreads();

#pragma unroll
        for (int kk = 0; kk < BK; kk++) {
            float2 xv2 = *(const float2*)&xsT[kk * XPAD + 2 * ty];
            float4 wv4 = *(const float4*)&wsT[kk * WPAD + 4 * tx];
            acc[0][0] += xv2.x * wv4.x;
            acc[0][1] += xv2.x * wv4.y;
            acc[0][2] += xv2.x * wv4.z;
            acc[0][3] += xv2.x * wv4.w;
            acc[1][0] += xv2.y * wv4.x;
            acc[1][1] += xv2.y * wv4.y;
            acc[1][2] += xv2.y * wv4.z;
            acc[1][3] += xv2.y * wv4.w;
        }
    }

    __syncthreads();
    float* lg = sm;                   // logits [32][65]
#pragma unroll
    for (int i = 0; i < 2; i++)
#pragma unroll
        for (int j = 0; j < 4; j++)
            lg[(2 * ty + i) * 65 + 4 * tx + j] = acc[i][j];
    __syncthreads();

    if (tid < BT) {
        int t = tok0 + tid;
        float v0 = -3.4e38f, v1 = -3.4e38f;
        int e0 = 0, e1 = 0;
#pragma unroll
        for (int e = 0; e < N_EXP; e++) {
            float v = lg[tid * 65 + e];
            if (v > v0)      { v1 = v0; e1 = e0; v0 = v; e0 = e; }
            else if (v > v1) { v1 = v;  e1 = e; }
        }
        float r  = expf(v1 - v0);
        float p0 = 1.f / (1.f + r);
        float p1 = r * p0;
        g_te[2 * t]     = e0;
        g_te[2 * t + 1] = e1;
        g_tw[2 * t]     = p0;
        g_tw[2 * t + 1] = p1;
    }
}

// ---------------- Kernel B: order-exact capacity assignment -----------------
__global__ void __launch_bounds__(256) assign_kernel(float* __restrict__ out)
{
    int e    = blockIdx.x;            // expert 0..63
    int tid  = threadIdx.x;
    int lane = tid & 31;
    int wid  = tid >> 5;

    int ids[32];
    const int4* te4 = (const int4*)g_te;
#pragma unroll
    for (int k = 0; k < 8; k++) {
        int4 v = te4[tid * 8 + k];
        ids[4 * k + 0] = v.x; ids[4 * k + 1] = v.y;
        ids[4 * k + 2] = v.z; ids[4 * k + 3] = v.w;
    }

    int cnt = 0;
#pragma unroll
    for (int k = 0; k < 32; k++) cnt += (ids[k] == e);

    int c = cnt;
#pragma unroll
    for (int o = 1; o < 32; o <<= 1) {
        int n = __shfl_up_sync(0xffffffffu, c, o);
        if (lane >= o) c += n;
    }
    __shared__ int wsum[8];
    if (lane == 31) wsum[wid] = c;
    __syncthreads();
    if (wid == 0 && lane < 8) {
        int v = wsum[lane];
#pragma unroll
        for (int o = 1; o < 8; o <<= 1) {
            int n = __shfl_up_sync(0xffu, v, o);
            if (lane >= o) v += n;
        }
        wsum[lane] = v;
    }
    __syncthreads();
    int prefix = c - cnt + (wid ? wsum[wid - 1] : 0);
    int total  = wsum[7];

    float* cb = out + N_EXP;
    float* mk = out + N_EXP + TEC;
    int slot = prefix;
#pragma unroll
    for (int k = 0; k < 32; k++) {
        if (ids[k] == e) {
            if (slot < CAP) {
                int a = tid * 32 + k;
                int t = a >> 1;
                size_t idx = (size_t)t * (N_EXP * CAP) + (size_t)e * CAP + slot;
                cb[idx] = g_tw[a];
                mk[idx] = 1.0f;
            }
            slot++;
        }
    }

    if (tid == 0)
        out[e] = (float)(total < CAP ? total : CAP);
}

// ---------------- host-side fork/join plumbing ------------------------------
namespace {
struct Plumbing {
    cudaStream_t sA, sB;
    cudaEvent_t  eFork, eJoinA, eJoinB;
    Plumbing() {
        cudaStreamCreateWithFlags(&sA, cudaStreamNonBlocking);
        cudaStreamCreateWithFlags(&sB, cudaStreamNonBlocking);
        cudaEventCreateWithFlags(&eFork,  cudaEventDisableTiming);
        cudaEventCreateWithFlags(&eJoinA, cudaEventDisableTiming);
        cudaEventCreateWithFlags(&eJoinB, cudaEventDisableTiming);
    }
};
}

extern "C" void kernel_launch(void* const* d_in, const int* in_sizes, int n_in,
                              void* d_out, int out_size)
{
    static Plumbing P;   // host-side objects only; created on first (uncaptured) call

    const float* x  = (const float*)d_in[0];
    const float* wg = (const float*)d_in[1];
    float* out = (float*)d_out;

    size_t bytes = (size_t)out_size * sizeof(float);
    size_t half  = (bytes / 2) & ~(size_t)255;

    // fork: side streams join the capture via event wait
    cudaEventRecord(P.eFork, 0);
    cudaStreamWaitEvent(P.sA, P.eFork, 0);
    cudaStreamWaitEvent(P.sB, P.eFork, 0);

    // parallel: two memset halves + GEMM (independent work)
    cudaMemsetAsync(out, 0, half, P.sA);
    cudaMemsetAsync((char*)out + half, 0, bytes - half, P.sB);
    gemm_kernel<<<GEMM_BLOCKS, 256>>>(x, wg);

    // join both side streams back into the main stream
    cudaEventRecord(P.eJoinA, P.sA);
    cudaEventRecord(P.eJoinB, P.sB);
    cudaStreamWaitEvent(0, P.eJoinA, 0);
    cudaStreamWaitEvent(0, P.eJoinB, 0);

    assign_kernel<<<N_EXP, 256>>>(out);
}

// round 10
// speedup vs baseline: 3.1421x; 3.1421x over previous
#include <cuda_runtime.h>

#define T_TOK 4096
#define D_DIM 2048
#define N_EXP 64
#define TOPK  2
#define CAP   160
#define TEC   (T_TOK * N_EXP * CAP)   // 41,943,040

// scratch (device globals; no allocation allowed)
__device__ int   g_te[T_TOK * TOPK];
__device__ float g_tw[T_TOK * TOPK];

#define BT 32
#define BK 32
#define GEMM_BLOCKS (T_TOK / BT)   // 128
#define FILL_BLOCKS 320
#define XPAD 34
#define WPAD 68

// Interleaved grid-stride fill of [lo4, hi4) by nblk CTAs (bid in [0,nblk)).
// Plain 128-bit stores; interleave keeps DRAM streams coalesced (slab layout
// measured ~1.6x slower in R5).
__device__ __forceinline__ void fill_strided(float4* __restrict__ o4,
                                             size_t lo4, size_t hi4,
                                             int nblk, int bid)
{
    size_t nth = (size_t)nblk * 256;
    size_t i   = lo4 + (size_t)bid * 256 + threadIdx.x;
    float4 z = make_float4(0.f, 0.f, 0.f, 0.f);
    for (; i < hi4; i += nth)
        o4[i] = z;
}

// Kernel 1: fused GEMM(+top2+softmax) + weighted-split zero-fill.
// CTAs 128..447: fill first 2/3 of buffer starting at t=0.
// CTAs 0..127:   gemm tile, then fill last 1/3 (their 40us-late start is
//                compensated by the half-size share -> all finish together).
__global__ void __launch_bounds__(256) gemm_fill_kernel(
    const float* __restrict__ x, const float* __restrict__ wg,
    float* __restrict__ out, int out_size)
{
    size_t n4    = (size_t)out_size >> 2;                 // 20,971,536
    size_t split = ((n4 * 2) / 3) & ~(size_t)31;          // 2/3, warp-aligned

    if (blockIdx.x >= GEMM_BLOCKS) {
        fill_strided((float4*)out, 0, split, FILL_BLOCKS, blockIdx.x - GEMM_BLOCKS);
        return;
    }

    // ---- GEMM path: 32 tokens x 64 experts per block ----
    __shared__ __align__(16) float sm[BK * XPAD + BK * WPAD];
    float* xsT = sm;                  // [BK][XPAD]
    float* wsT = sm + BK * XPAD;      // [BK][WPAD]

    int tid = threadIdx.x;
    int tx  = tid & 15;
    int ty  = tid >> 4;
    int tok0 = blockIdx.x * BT;

    float acc[2][4];
#pragma unroll
    for (int i = 0; i < 2; i++)
#pragma unroll
        for (int j = 0; j < 4; j++) acc[i][j] = 0.f;

    int xrow = tid >> 3;
    int c4   = tid & 7;

    for (int d0 = 0; d0 < D_DIM; d0 += BK) {
        float4 xv  = *(const float4*)&x [(size_t)(tok0 + xrow) * D_DIM + d0 + 4 * c4];
        float4 wv0 = *(const float4*)&wg[(size_t)(tid >> 3)        * D_DIM + d0 + 4 * c4];
        float4 wv1 = *(const float4*)&wg[(size_t)((tid >> 3) + 32) * D_DIM + d0 + 4 * c4];

        __syncthreads();
        xsT[(4 * c4 + 0) * XPAD + xrow] = xv.x;
        xsT[(4 * c4 + 1) * XPAD + xrow] = xv.y;
        xsT[(4 * c4 + 2) * XPAD + xrow] = xv.z;
        xsT[(4 * c4 + 3) * XPAD + xrow] = xv.w;
        int e0r = tid >> 3;
        wsT[(4 * c4 + 0) * WPAD + e0r] = wv0.x;
        wsT[(4 * c4 + 1) * WPAD + e0r] = wv0.y;
        wsT[(4 * c4 + 2) * WPAD + e0r] = wv0.z;
        wsT[(4 * c4 + 3) * WPAD + e0r] = wv0.w;
        wsT[(4 * c4 + 0) * WPAD + e0r + 32] = wv1.x;
        wsT[(4 * c4 + 1) * WPAD + e0r + 32] = wv1.y;
        wsT[(4 * c4 + 2) * WPAD + e0r + 32] = wv1.z;
        wsT[(4 * c4 + 3) * WPAD + e0r + 32] = wv1.w;
        __syncthreads();

#pragma unroll
        for (int kk = 0; kk < BK; kk++) {
            float2 xv2 = *(const float2*)&xsT[kk * XPAD + 2 * ty];
            float4 wv4 = *(const float4*)&wsT[kk * WPAD + 4 * tx];
            acc[0][0] += xv2.x * wv4.x;
            acc[0][1] += xv2.x * wv4.y;
            acc[0][2] += xv2.x * wv4.z;
            acc[0][3] += xv2.x * wv4.w;
            acc[1][0] += xv2.y * wv4.x;
            acc[1][1] += xv2.y * wv4.y;
            acc[1][2] += xv2.y * wv4.z;
            acc[1][3] += xv2.y * wv4.w;
        }
    }

    // ---- top-2 + softmax per token ----
    __syncthreads();
    float* lg = sm;                   // logits [32][65]
#pragma unroll
    for (int i = 0; i < 2; i++)
#pragma unroll
        for (int j = 0; j < 4; j++)
            lg[(2 * ty + i) * 65 + 4 * tx + j] = acc[i][j];
    __syncthreads();

    if (tid < BT) {
        int t = tok0 + tid;
        float v0 = -3.4e38f, v1 = -3.4e38f;
        int e0 = 0, e1 = 0;
#pragma unroll
        for (int e = 0; e < N_EXP; e++) {
            float v = lg[tid * 65 + e];
            if (v > v0)      { v1 = v0; e1 = e0; v0 = v; e0 = e; }
            else if (v > v1) { v1 = v;  e1 = e; }
        }
        float r  = expf(v1 - v0);
        float p0 = 1.f / (1.f + r);
        float p1 = r * p0;
        g_te[2 * t]     = e0;
        g_te[2 * t + 1] = e1;
        g_tw[2 * t]     = p0;
        g_tw[2 * t + 1] = p1;
    }

    // gemm CTA joins the fill: last 1/3 of the buffer (half-weight share).
    fill_strided((float4*)out, split, n4, GEMM_BLOCKS, blockIdx.x);

    if (blockIdx.x == 0 && tid < (out_size & 3))
        out[(n4 << 2) + tid] = 0.f;
}

// Kernel 2: order-exact parallel capacity assignment.
__global__ void __launch_bounds__(256) assign_kernel(float* __restrict__ out)
{
    int e    = blockIdx.x;            // expert 0..63
    int tid  = threadIdx.x;
    int lane = tid & 31;
    int wid  = tid >> 5;

    int ids[32];
    const int4* te4 = (const int4*)g_te;
#pragma unroll
    for (int k = 0; k < 8; k++) {
        int4 v = te4[tid * 8 + k];
        ids[4 * k + 0] = v.x; ids[4 * k + 1] = v.y;
        ids[4 * k + 2] = v.z; ids[4 * k + 3] = v.w;
    }

    int cnt = 0;
#pragma unroll
    for (int k = 0; k < 32; k++) cnt += (ids[k] == e);

    int c = cnt;
#pragma unroll
    for (int o = 1; o < 32; o <<= 1) {
        int n = __shfl_up_sync(0xffffffffu, c, o);
        if (lane >= o) c += n;
    }
    __shared__ int wsum[8];
    if (lane == 31) wsum[wid] = c;
    __syncthreads();
    if (wid == 0 && lane < 8) {
        int v = wsum[lane];
#pragma unroll
        for (int o = 1; o < 8; o <<= 1) {
            int n = __shfl_up_sync(0xffu, v, o);
            if (lane >= o) v += n;
        }
        wsum[lane] = v;
    }
    __syncthreads();
    int prefix = c - cnt + (wid ? wsum[wid - 1] : 0);
    int total  = wsum[7];

    float* cb = out + N_EXP;
    float* mk = out + N_EXP + TEC;
    int slot = prefix;
#pragma unroll
    for (int k = 0; k < 32; k++) {
        if (ids[k] == e) {
            if (slot < CAP) {
                int a = tid * 32 + k;
                int t = a >> 1;
                size_t idx = (size_t)t * (N_EXP * CAP) + (size_t)e * CAP + slot;
                cb[idx] = g_tw[a];
                mk[idx] = 1.0f;
            }
            slot++;
        }
    }

    if (tid == 0)
        out[e] = (float)(total < CAP ? total : CAP);
}

extern "C" void kernel_launch(void* const* d_in, const int* in_sizes, int n_in,
                              void* d_out, int out_size)
{
    const float* x  = (const float*)d_in[0];
    const float* wg = (const float*)d_in[1];
    float* out = (float*)d_out;

    gemm_fill_kernel<<<GEMM_BLOCKS + FILL_BLOCKS, 256>>>(x, wg, out, out_size);
    assign_kernel<<<N_EXP, 256>>>(out);
}

// round 11
// speedup vs baseline: 3.7100x; 1.1807x over previous
#include <cuda_runtime.h>
#include <cstdint>

#define T_TOK 4096
#define D_DIM 2048
#define N_EXP 64
#define TOPK  2
#define CAP   160
#define TEC   (T_TOK * N_EXP * CAP)   // 41,943,040

// scratch (device globals; no allocation allowed)
__device__ int   g_te[T_TOK * TOPK];
__device__ float g_tw[T_TOK * TOPK];

#define BT 32
#define BK 32
#define GEMM_BLOCKS (T_TOK / BT)   // 128
#define XPAD 34
#define WPAD 68

#define FILL_CHUNK   32768         // bytes per bulk store
#define FILL_GRID    640           // 10240 chunks / 640 = 16 per CTA (exact)

// ---------------- Kernel A: GEMM + top2 + softmax ---------------------------
__global__ void __launch_bounds__(256) gemm_kernel(
    const float* __restrict__ x, const float* __restrict__ wg)
{
    __shared__ __align__(16) float sm[BK * XPAD + BK * WPAD];
    float* xsT = sm;                  // [BK][XPAD]
    float* wsT = sm + BK * XPAD;      // [BK][WPAD]

    int tid = threadIdx.x;
    int tx  = tid & 15;
    int ty  = tid >> 4;
    int tok0 = blockIdx.x * BT;

    float acc[2][4];
#pragma unroll
    for (int i = 0; i < 2; i++)
#pragma unroll
        for (int j = 0; j < 4; j++) acc[i][j] = 0.f;

    int xrow = tid >> 3;
    int c4   = tid & 7;

    for (int d0 = 0; d0 < D_DIM; d0 += BK) {
        float4 xv  = *(const float4*)&x [(size_t)(tok0 + xrow) * D_DIM + d0 + 4 * c4];
        float4 wv0 = *(const float4*)&wg[(size_t)(tid >> 3)        * D_DIM + d0 + 4 * c4];
        float4 wv1 = *(const float4*)&wg[(size_t)((tid >> 3) + 32) * D_DIM + d0 + 4 * c4];

        __syncthreads();
        xsT[(4 * c4 + 0) * XPAD + xrow] = xv.x;
        xsT[(4 * c4 + 1) * XPAD + xrow] = xv.y;
        xsT[(4 * c4 + 2) * XPAD + xrow] = xv.z;
        xsT[(4 * c4 + 3) * XPAD + xrow] = xv.w;
        int e0r = tid >> 3;
        wsT[(4 * c4 + 0) * WPAD + e0r] = wv0.x;
        wsT[(4 * c4 + 1) * WPAD + e0r] = wv0.y;
        wsT[(4 * c4 + 2) * WPAD + e0r] = wv0.z;
        wsT[(4 * c4 + 3) * WPAD + e0r] = wv0.w;
        wsT[(4 * c4 + 0) * WPAD + e0r + 32] = wv1.x;
        wsT[(4 * c4 + 1) * WPAD + e0r + 32] = wv1.y;
        wsT[(4 * c4 + 2) * WPAD + e0r + 32] = wv1.z;
        wsT[(4 * c4 + 3) * WPAD + e0r + 32] = wv1.w;
        __syncthreads();

#pragma unroll
        for (int kk = 0; kk < BK; kk++) {
            float2 xv2 = *(const float2*)&xsT[kk * XPAD + 2 * ty];
            float4 wv4 = *(const float4*)&wsT[kk * WPAD + 4 * tx];
            acc[0][0] += xv2.x * wv4.x;
            acc[0][1] += xv2.x * wv4.y;
            acc[0][2] += xv2.x * wv4.z;
            acc[0][3] += xv2.x * wv4.w;
            acc[1][0] += xv2.y * wv4.x;
            acc[1][1] += xv2.y * wv4.y;
            acc[1][2] += xv2.y * wv4.z;
            acc[1][3] += xv2.y * wv4.w;
        }
    }

    __syncthreads();
    float* lg = sm;                   // logits [32][65]
#pragma unroll
    for (int i = 0; i < 2; i++)
#pragma unroll
        for (int j = 0; j < 4; j++)
            lg[(2 * ty + i) * 65 + 4 * tx + j] = acc[i][j];
    __syncthreads();

    if (tid < BT) {
        int t = tok0 + tid;
        float v0 = -3.4e38f, v1 = -3.4e38f;
        int e0 = 0, e1 = 0;
#pragma unroll
        for (int e = 0; e < N_EXP; e++) {
            float v = lg[tid * 65 + e];
            if (v > v0)      { v1 = v0; e1 = e0; v0 = v; e0 = e; }
            else if (v > v1) { v1 = v;  e1 = e; }
        }
        float r  = expf(v1 - v0);
        float p0 = 1.f / (1.f + r);
        float p1 = r * p0;
        g_te[2 * t]     = e0;
        g_te[2 * t + 1] = e1;
        g_tw[2 * t]     = p0;
        g_tw[2 * t + 1] = p1;
    }
}

// ---------------- Kernel B: TMA bulk-store zero-fill ------------------------
// Each CTA zeroes a 32KB SMEM buffer once, then issues cp.async.bulk S->G
// copies. Bulk-async path bypasses the SM store queue / L2 write-allocate.
__global__ void __launch_bounds__(32) tma_fill_kernel(float* __restrict__ out, int out_size)
{
    __shared__ __align__(1024) float4 zbuf[FILL_CHUNK / 16];

    for (int i = threadIdx.x; i < FILL_CHUNK / 16; i += 32)
        zbuf[i] = make_float4(0.f, 0.f, 0.f, 0.f);
    __syncwarp();
    asm volatile("fence.proxy.async.shared::cta;" ::: "memory");

    size_t   bytes = (size_t)out_size * sizeof(float);
    unsigned nch   = (unsigned)(bytes / FILL_CHUNK);       // 10240 here (exact)
    uint32_t saddr = (uint32_t)__cvta_generic_to_shared(zbuf);

    if (threadIdx.x == 0) {
        for (unsigned c = blockIdx.x; c < nch; c += gridDim.x) {
            char* dst = (char*)out + (size_t)c * FILL_CHUNK;
            asm volatile(
                "cp.async.bulk.global.shared::cta.bulk_group [%0], [%1], %2;"
                :: "l"(dst), "r"(saddr), "r"((unsigned)FILL_CHUNK) : "memory");
        }
        asm volatile("cp.async.bulk.commit_group;" ::: "memory");
        asm volatile("cp.async.bulk.wait_group 0;" ::: "memory");
    }

    // generic tail (bytes % FILL_CHUNK) — zero here, kept for safety
    size_t tail = bytes % FILL_CHUNK;
    if (tail && blockIdx.x == 0) {
        char* p = (char*)out + bytes - tail;
        for (size_t i = threadIdx.x * 4; i + 3 < tail; i += 128)
            *(float*)(p + i) = 0.f;
    }
}

// ---------------- Kernel C: order-exact capacity assignment -----------------
__global__ void __launch_bounds__(256) assign_kernel(float* __restrict__ out)
{
    int e    = blockIdx.x;            // expert 0..63
    int tid  = threadIdx.x;
    int lane = tid & 31;
    int wid  = tid >> 5;

    int ids[32];
    const int4* te4 = (const int4*)g_te;
#pragma unroll
    for (int k = 0; k < 8; k++) {
        int4 v = te4[tid * 8 + k];
        ids[4 * k + 0] = v.x; ids[4 * k + 1] = v.y;
        ids[4 * k + 2] = v.z; ids[4 * k + 3] = v.w;
    }

    int cnt = 0;
#pragma unroll
    for (int k = 0; k < 32; k++) cnt += (ids[k] == e);

    int c = cnt;
#pragma unroll
    for (int o = 1; o < 32; o <<= 1) {
        int n = __shfl_up_sync(0xffffffffu, c, o);
        if (lane >= o) c += n;
    }
    __shared__ int wsum[8];
    if (lane == 31) wsum[wid] = c;
    __syncthreads();
    if (wid == 0 && lane < 8) {
        int v = wsum[lane];
#pragma unroll
        for (int o = 1; o < 8; o <<= 1) {
            int n = __shfl_up_sync(0xffu, v, o);
            if (lane >= o) v += n;
        }
        wsum[lane] = v;
    }
    __syncthreads();
    int prefix = c - cnt + (wid ? wsum[wid - 1] : 0);
    int total  = wsum[7];

    float* cb = out + N_EXP;
    float* mk = out + N_EXP + TEC;
    int slot = prefix;
#pragma unroll
    for (int k = 0; k < 32; k++) {
        if (ids[k] == e) {
            if (slot < CAP) {
                int a = tid * 32 + k;
                int t = a >> 1;
                size_t idx = (size_t)t * (N_EXP * CAP) + (size_t)e * CAP + slot;
                cb[idx] = g_tw[a];
                mk[idx] = 1.0f;
            }
            slot++;
        }
    }

    if (tid == 0)
        out[e] = (float)(total < CAP ? total : CAP);
}

extern "C" void kernel_launch(void* const* d_in, const int* in_sizes, int n_in,
                              void* d_out, int out_size)
{
    const float* x  = (const float*)d_in[0];
    const float* wg = (const float*)d_in[1];
    float* out = (float*)d_out;

    gemm_kernel<<<GEMM_BLOCKS, 256>>>(x, wg);
    tma_fill_kernel<<<FILL_GRID, 32>>>(out, out_size);
    assign_kernel<<<N_EXP, 256>>>(out);
}

// round 12
// speedup vs baseline: 4.1698x; 1.1239x over previous
#include <cuda_runtime.h>
#include <cstdint>

#define T_TOK 4096
#define D_DIM 2048
#define N_EXP 64
#define TOPK  2
#define CAP   160
#define TEC   (T_TOK * N_EXP * CAP)   // 41,943,040

// scratch (device globals; no allocation allowed)
__device__ int   g_te[T_TOK * TOPK];
__device__ float g_tw[T_TOK * TOPK];
__device__ float g_part[2][T_TOK][N_EXP];   // K-split partial logits (2 MB)

#define BT 32
#define BK 32
#define KSPLIT 2
#define KHALF (D_DIM / KSPLIT)     // 1024
#define GEMM_BLOCKS (T_TOK / BT * KSPLIT)   // 256
#define XPAD 34
#define WPAD 68

#define FILL_CHUNK   32768         // bytes per bulk store
#define FILL_GRID    640           // 10240 chunks / 640 = 16 per CTA (exact)

// ---------------- Kernel A: K-split GEMM -> partial logits ------------------
__global__ void __launch_bounds__(256) gemm_kernel(
    const float* __restrict__ x, const float* __restrict__ wg)
{
    __shared__ __align__(16) float sm[BK * XPAD + BK * WPAD];
    float* xsT = sm;                  // [BK][XPAD]
    float* wsT = sm + BK * XPAD;      // [BK][WPAD]

    int tid = threadIdx.x;
    int tx  = tid & 15;
    int ty  = tid >> 4;
    int kh    = blockIdx.x & 1;                   // K half
    int tok0  = (blockIdx.x >> 1) * BT;
    int kbase = kh * KHALF;

    float acc[2][4];
#pragma unroll
    for (int i = 0; i < 2; i++)
#pragma unroll
        for (int j = 0; j < 4; j++) acc[i][j] = 0.f;

    int xrow = tid >> 3;
    int c4   = tid & 7;

    for (int d0 = kbase; d0 < kbase + KHALF; d0 += BK) {
        float4 xv  = *(const float4*)&x [(size_t)(tok0 + xrow) * D_DIM + d0 + 4 * c4];
        float4 wv0 = *(const float4*)&wg[(size_t)(tid >> 3)        * D_DIM + d0 + 4 * c4];
        float4 wv1 = *(const float4*)&wg[(size_t)((tid >> 3) + 32) * D_DIM + d0 + 4 * c4];

        __syncthreads();
        xsT[(4 * c4 + 0) * XPAD + xrow] = xv.x;
        xsT[(4 * c4 + 1) * XPAD + xrow] = xv.y;
        xsT[(4 * c4 + 2) * XPAD + xrow] = xv.z;
        xsT[(4 * c4 + 3) * XPAD + xrow] = xv.w;
        int e0r = tid >> 3;
        wsT[(4 * c4 + 0) * WPAD + e0r] = wv0.x;
        wsT[(4 * c4 + 1) * WPAD + e0r] = wv0.y;
        wsT[(4 * c4 + 2) * WPAD + e0r] = wv0.z;
        wsT[(4 * c4 + 3) * WPAD + e0r] = wv0.w;
        wsT[(4 * c4 + 0) * WPAD + e0r + 32] = wv1.x;
        wsT[(4 * c4 + 1) * WPAD + e0r + 32] = wv1.y;
        wsT[(4 * c4 + 2) * WPAD + e0r + 32] = wv1.z;
        wsT[(4 * c4 + 3) * WPAD + e0r + 32] = wv1.w;
        __syncthreads();

#pragma unroll
        for (int kk = 0; kk < BK; kk++) {
            float2 xv2 = *(const float2*)&xsT[kk * XPAD + 2 * ty];
            float4 wv4 = *(const float4*)&wsT[kk * WPAD + 4 * tx];
            acc[0][0] += xv2.x * wv4.x;
            acc[0][1] += xv2.x * wv4.y;
            acc[0][2] += xv2.x * wv4.z;
            acc[0][3] += xv2.x * wv4.w;
            acc[1][0] += xv2.y * wv4.x;
            acc[1][1] += xv2.y * wv4.y;
            acc[1][2] += xv2.y * wv4.z;
            acc[1][3] += xv2.y * wv4.w;
        }
    }

    // write partial logits (coalesced float4 per row-half)
    *(float4*)&g_part[kh][tok0 + 2 * ty    ][4 * tx] =
        make_float4(acc[0][0], acc[0][1], acc[0][2], acc[0][3]);
    *(float4*)&g_part[kh][tok0 + 2 * ty + 1][4 * tx] =
        make_float4(acc[1][0], acc[1][1], acc[1][2], acc[1][3]);
}

// ---------------- Kernel B: sum halves + top2 + softmax ---------------------
__global__ void __launch_bounds__(256) top2_kernel()
{
    int t = blockIdx.x * 256 + threadIdx.x;    // token id

    const float4* pa = (const float4*)&g_part[0][t][0];
    const float4* pb = (const float4*)&g_part[1][t][0];

    float v0 = -3.4e38f, v1 = -3.4e38f;
    int e0 = 0, e1 = 0;
#pragma unroll
    for (int i = 0; i < N_EXP / 4; i++) {
        float4 va = pa[i], vb = pb[i];
        float s[4] = { va.x + vb.x, va.y + vb.y, va.z + vb.z, va.w + vb.w };
#pragma unroll
        for (int j = 0; j < 4; j++) {
            float v = s[j];
            int   e = 4 * i + j;
            if (v > v0)      { v1 = v0; e1 = e0; v0 = v; e0 = e; }
            else if (v > v1) { v1 = v;  e1 = e; }
        }
    }
    float r  = expf(v1 - v0);
    float p0 = 1.f / (1.f + r);
    float p1 = r * p0;
    g_te[2 * t]     = e0;
    g_te[2 * t + 1] = e1;
    g_tw[2 * t]     = p0;
    g_tw[2 * t + 1] = p1;
}

// ---------------- Kernel C: TMA bulk-store zero-fill ------------------------
__global__ void __launch_bounds__(32) tma_fill_kernel(float* __restrict__ out, int out_size)
{
    __shared__ __align__(1024) float4 zbuf[FILL_CHUNK / 16];

    for (int i = threadIdx.x; i < FILL_CHUNK / 16; i += 32)
        zbuf[i] = make_float4(0.f, 0.f, 0.f, 0.f);
    __syncwarp();
    asm volatile("fence.proxy.async.shared::cta;" ::: "memory");

    size_t   bytes = (size_t)out_size * sizeof(float);
    unsigned nch   = (unsigned)(bytes / FILL_CHUNK);       // 10240 (exact)
    uint32_t saddr = (uint32_t)__cvta_generic_to_shared(zbuf);

    if (threadIdx.x == 0) {
        for (unsigned c = blockIdx.x; c < nch; c += gridDim.x) {
            char* dst = (char*)out + (size_t)c * FILL_CHUNK;
            asm volatile(
                "cp.async.bulk.global.shared::cta.bulk_group [%0], [%1], %2;"
                :: "l"(dst), "r"(saddr), "r"((unsigned)FILL_CHUNK) : "memory");
        }
        asm volatile("cp.async.bulk.commit_group;" ::: "memory");
        asm volatile("cp.async.bulk.wait_group 0;" ::: "memory");
    }

    size_t tail = bytes % FILL_CHUNK;
    if (tail && blockIdx.x == 0) {
        char* p = (char*)out + bytes - tail;
        for (size_t i = threadIdx.x * 4; i + 3 < tail; i += 128)
            *(float*)(p + i) = 0.f;
    }
}

// ---------------- Kernel D: order-exact capacity assignment -----------------
__global__ void __launch_bounds__(256) assign_kernel(float* __restrict__ out)
{
    int e    = blockIdx.x;            // expert 0..63
    int tid  = threadIdx.x;
    int lane = tid & 31;
    int wid  = tid >> 5;

    int ids[32];
    const int4* te4 = (const int4*)g_te;
#pragma unroll
    for (int k = 0; k < 8; k++) {
        int4 v = te4[tid * 8 + k];
        ids[4 * k + 0] = v.x; ids[4 * k + 1] = v.y;
        ids[4 * k + 2] = v.z; ids[4 * k + 3] = v.w;
    }

    int cnt = 0;
#pragma unroll
    for (int k = 0; k < 32; k++) cnt += (ids[k] == e);

    int c = cnt;
#pragma unroll
    for (int o = 1; o < 32; o <<= 1) {
        int n = __shfl_up_sync(0xffffffffu, c, o);
        if (lane >= o) c += n;
    }
    __shared__ int wsum[8];
    if (lane == 31) wsum[wid] = c;
    __syncthreads();
    if (wid == 0 && lane < 8) {
        int v = wsum[lane];
#pragma unroll
        for (int o = 1; o < 8; o <<= 1) {
            int n = __shfl_up_sync(0xffu, v, o);
            if (lane >= o) v += n;
        }
        wsum[lane] = v;
    }
    __syncthreads();
    int prefix = c - cnt + (wid ? wsum[wid - 1] : 0);
    int total  = wsum[7];

    float* cb = out + N_EXP;
    float* mk = out + N_EXP + TEC;
    int slot = prefix;
#pragma unroll
    for (int k = 0; k < 32; k++) {
        if (ids[k] == e) {
            if (slot < CAP) {
                int a = tid * 32 + k;
                int t = a >> 1;
                size_t idx = (size_t)t * (N_EXP * CAP) + (size_t)e * CAP + slot;
                cb[idx] = g_tw[a];
                mk[idx] = 1.0f;
            }
            slot++;
        }
    }

    if (tid == 0)
        out[e] = (float)(total < CAP ? total : CAP);
}

extern "C" void kernel_launch(void* const* d_in, const int* in_sizes, int n_in,
                              void* d_out, int out_size)
{
    const float* x  = (const float*)d_in[0];
    const float* wg = (const float*)d_in[1];
    float* out = (float*)d_out;

    gemm_kernel<<<GEMM_BLOCKS, 256>>>(x, wg);
    top2_kernel<<<T_TOK / 256, 256>>>();
    tma_fill_kernel<<<FILL_GRID, 32>>>(out, out_size);
    assign_kernel<<<N_EXP, 256>>>(out);
}

// round 13
// speedup vs baseline: 5.3012x; 1.2713x over previous
#include <cuda_runtime.h>
#include <cstdint>

#define T_TOK 4096
#define D_DIM 2048
#define N_EXP 64
#define TOPK  2
#define CAP   160
#define TEC   (T_TOK * N_EXP * CAP)   // 41,943,040

// scratch (device globals; no allocation allowed)
__device__ int   g_te[T_TOK * TOPK];
__device__ float g_tw[T_TOK * TOPK];
__device__ float g_part[2][T_TOK][N_EXP];   // K-split partial logits (2 MB)

#define BT 32
#define BK 32
#define KSPLIT 2
#define KHALF (D_DIM / KSPLIT)              // 1024
#define GEMM_BLOCKS (T_TOK / BT * KSPLIT)   // 256
#define XPAD 34
#define WPAD 68

#define FILL_CHUNK  32768                   // bytes per bulk store
#define FILL_BLOCKS 320                     // 10240 chunks / 320 = 32 each (exact)

// ---------------- Kernel A: fused K-split GEMM + TMA bulk-store fill --------
// CTAs [0, FILL_BLOCKS): zero-fill the output via cp.async.bulk S->G (TMA
//   engine path, ~6 TB/s, near-zero SM footprint).
// CTAs [FILL_BLOCKS, +GEMM_BLOCKS): K-split GEMM -> partial logits.
// Disjoint resources -> phases overlap inside one launch; fill completion is
// guaranteed at kernel end (wait_group 0), so assign can run next.
__global__ void __launch_bounds__(256) gemm_fill_kernel(
    const float* __restrict__ x, const float* __restrict__ wg,
    float* __restrict__ out, int out_size)
{
    __shared__ __align__(1024) float smbuf[FILL_CHUNK / 4];   // 32 KB, both roles

    if (blockIdx.x < FILL_BLOCKS) {
        // ---- TMA fill role ----
        float4* zb = (float4*)smbuf;
        for (int i = threadIdx.x; i < FILL_CHUNK / 16; i += 256)
            zb[i] = make_float4(0.f, 0.f, 0.f, 0.f);
        __syncthreads();
        asm volatile("fence.proxy.async.shared::cta;" ::: "memory");

        size_t   bytes = (size_t)out_size * sizeof(float);
        unsigned nch   = (unsigned)(bytes / FILL_CHUNK);     // 10240 (exact here)
        uint32_t saddr = (uint32_t)__cvta_generic_to_shared(smbuf);

        if (threadIdx.x == 0) {
            for (unsigned c = blockIdx.x; c < nch; c += FILL_BLOCKS) {
                char* dst = (char*)out + (size_t)c * FILL_CHUNK;
                asm volatile(
                    "cp.async.bulk.global.shared::cta.bulk_group [%0], [%1], %2;"
                    :: "l"(dst), "r"(saddr), "r"((unsigned)FILL_CHUNK) : "memory");
            }
            asm volatile("cp.async.bulk.commit_group;" ::: "memory");
            asm volatile("cp.async.bulk.wait_group 0;" ::: "memory");
        }
        // tail (bytes % FILL_CHUNK) — zero for this shape; safe generic cover
        size_t tail = bytes % FILL_CHUNK;
        if (tail && blockIdx.x == 0) {
            char* p = (char*)out + bytes - tail;
            for (size_t i = threadIdx.x * 4; i + 3 < tail; i += 1024)
                *(float*)(p + i) = 0.f;
        }
        return;
    }

    // ---- GEMM role ----
    float* xsT = smbuf;                   // [BK][XPAD]
    float* wsT = smbuf + BK * XPAD;       // [BK][WPAD]

    int bid = blockIdx.x - FILL_BLOCKS;
    int tid = threadIdx.x;
    int tx  = tid & 15;
    int ty  = tid >> 4;
    int kh    = bid & 1;                  // K half
    int tok0  = (bid >> 1) * BT;
    int kbase = kh * KHALF;

    float acc[2][4];
#pragma unroll
    for (int i = 0; i < 2; i++)
#pragma unroll
        for (int j = 0; j < 4; j++) acc[i][j] = 0.f;

    int xrow = tid >> 3;
    int c4   = tid & 7;

    for (int d0 = kbase; d0 < kbase + KHALF; d0 += BK) {
        float4 xv  = *(const float4*)&x [(size_t)(tok0 + xrow) * D_DIM + d0 + 4 * c4];
        float4 wv0 = *(const float4*)&wg[(size_t)(tid >> 3)        * D_DIM + d0 + 4 * c4];
        float4 wv1 = *(const float4*)&wg[(size_t)((tid >> 3) + 32) * D_DIM + d0 + 4 * c4];

        __syncthreads();
        xsT[(4 * c4 + 0) * XPAD + xrow] = xv.x;
        xsT[(4 * c4 + 1) * XPAD + xrow] = xv.y;
        xsT[(4 * c4 + 2) * XPAD + xrow] = xv.z;
        xsT[(4 * c4 + 3) * XPAD + xrow] = xv.w;
        int e0r = tid >> 3;
        wsT[(4 * c4 + 0) * WPAD + e0r] = wv0.x;
        wsT[(4 * c4 + 1) * WPAD + e0r] = wv0.y;
        wsT[(4 * c4 + 2) * WPAD + e0r] = wv0.z;
        wsT[(4 * c4 + 3) * WPAD + e0r] = wv0.w;
        wsT[(4 * c4 + 0) * WPAD + e0r + 32] = wv1.x;
        wsT[(4 * c4 + 1) * WPAD + e0r + 32] = wv1.y;
        wsT[(4 * c4 + 2) * WPAD + e0r + 32] = wv1.z;
        wsT[(4 * c4 + 3) * WPAD + e0r + 32] = wv1.w;
        __syncthreads();

#pragma unroll
        for (int kk = 0; kk < BK; kk++) {
            float2 xv2 = *(const float2*)&xsT[kk * XPAD + 2 * ty];
            float4 wv4 = *(const float4*)&wsT[kk * WPAD + 4 * tx];
            acc[0][0] += xv2.x * wv4.x;
            acc[0][1] += xv2.x * wv4.y;
            acc[0][2] += xv2.x * wv4.z;
            acc[0][3] += xv2.x * wv4.w;
            acc[1][0] += xv2.y * wv4.x;
            acc[1][1] += xv2.y * wv4.y;
            acc[1][2] += xv2.y * wv4.z;
            acc[1][3] += xv2.y * wv4.w;
        }
    }

    *(float4*)&g_part[kh][tok0 + 2 * ty    ][4 * tx] =
        make_float4(acc[0][0], acc[0][1], acc[0][2], acc[0][3]);
    *(float4*)&g_part[kh][tok0 + 2 * ty + 1][4 * tx] =
        make_float4(acc[1][0], acc[1][1], acc[1][2], acc[1][3]);
}

// ---------------- Kernel B: sum halves + top2 + softmax ---------------------
__global__ void __launch_bounds__(256) top2_kernel()
{
    int t = blockIdx.x * 256 + threadIdx.x;    // token id

    const float4* pa = (const float4*)&g_part[0][t][0];
    const float4* pb = (const float4*)&g_part[1][t][0];

    float v0 = -3.4e38f, v1 = -3.4e38f;
    int e0 = 0, e1 = 0;
#pragma unroll
    for (int i = 0; i < N_EXP / 4; i++) {
        float4 va = pa[i], vb = pb[i];
        float s[4] = { va.x + vb.x, va.y + vb.y, va.z + vb.z, va.w + vb.w };
#pragma unroll
        for (int j = 0; j < 4; j++) {
            float v = s[j];
            int   e = 4 * i + j;
            if (v > v0)      { v1 = v0; e1 = e0; v0 = v; e0 = e; }
            else if (v > v1) { v1 = v;  e1 = e; }
        }
    }
    float r  = expf(v1 - v0);
    float p0 = 1.f / (1.f + r);
    float p1 = r * p0;
    g_te[2 * t]     = e0;
    g_te[2 * t + 1] = e1;
    g_tw[2 * t]     = p0;
    g_tw[2 * t + 1] = p1;
}

// ---------------- Kernel C: order-exact capacity assignment -----------------
__global__ void __launch_bounds__(256) assign_kernel(float* __restrict__ out)
{
    int e    = blockIdx.x;            // expert 0..63
    int tid  = threadIdx.x;
    int lane = tid & 31;
    int wid  = tid >> 5;

    int ids[32];
    const int4* te4 = (const int4*)g_te;
#pragma unroll
    for (int k = 0; k < 8; k++) {
        int4 v = te4[tid * 8 + k];
        ids[4 * k + 0] = v.x; ids[4 * k + 1] = v.y;
        ids[4 * k + 2] = v.z; ids[4 * k + 3] = v.w;
    }

    int cnt = 0;
#pragma unroll
    for (int k = 0; k < 32; k++) cnt += (ids[k] == e);

    int c = cnt;
#pragma unroll
    for (int o = 1; o < 32; o <<= 1) {
        int n = __shfl_up_sync(0xffffffffu, c, o);
        if (lane >= o) c += n;
    }
    __shared__ int wsum[8];
    if (lane == 31) wsum[wid] = c;
    __syncthreads();
    if (wid == 0 && lane < 8) {
        int v = wsum[lane];
#pragma unroll
        for (int o = 1; o < 8; o <<= 1) {
            int n = __shfl_up_sync(0xffu, v, o);
            if (lane >= o) v += n;
        }
        wsum[lane] = v;
    }
    __syncthreads();
    int prefix = c - cnt + (wid ? wsum[wid - 1] : 0);
    int total  = wsum[7];

    float* cb = out + N_EXP;
    float* mk = out + N_EXP + TEC;
    int slot = prefix;
#pragma unroll
    for (int k = 0; k < 32; k++) {
        if (ids[k] == e) {
            if (slot < CAP) {
                int a = tid * 32 + k;
                int t = a >> 1;
                size_t idx = (size_t)t * (N_EXP * CAP) + (size_t)e * CAP + slot;
                cb[idx] = g_tw[a];
                mk[idx] = 1.0f;
            }
            slot++;
        }
    }

    if (tid == 0)
        out[e] = (float)(total < CAP ? total : CAP);
}

extern "C" void kernel_launch(void* const* d_in, const int* in_sizes, int n_in,
                              void* d_out, int out_size)
{
    const float* x  = (const float*)d_in[0];
    const float* wg = (const float*)d_in[1];
    float* out = (float*)d_out;

    gemm_fill_kernel<<<FILL_BLOCKS + GEMM_BLOCKS, 256>>>(x, wg, out, out_size);
    top2_kernel<<<T_TOK / 256, 256>>>();
    assign_kernel<<<N_EXP, 256>>>(out);
}

// round 14
// speedup vs baseline: 7.0512x; 1.3301x over previous
#include <cuda_runtime.h>
#include <cstdint>

#define T_TOK 4096
#define D_DIM 2048
#define N_EXP 64
#define TOPK  2
#define CAP   160
#define TEC   (T_TOK * N_EXP * CAP)   // 41,943,040

#define KSPLIT 4
#define KQ    (D_DIM / KSPLIT)        // 512
#define BT    64                      // tokens per CTA
#define BK    32                      // K per tile
#define XP    68                      // smem row stride (floats): 272B, 16B-aligned
#define GEMM_BLOCKS (T_TOK / BT * KSPLIT)   // 256

#define FILL_CHUNK  32768
#define FILL_BLOCKS 320               // 10240 chunks / 320 = 32 each (exact)

// scratch (device globals; no allocation allowed)
__device__ int   g_te[T_TOK * TOPK];
__device__ float g_tw[T_TOK * TOPK];
__device__ float g_part[KSPLIT][T_TOK][N_EXP];   // partial logits (4 MB)

__device__ __forceinline__ void ffma2(unsigned long long& d,
                                      unsigned long long a, unsigned long long b)
{
    asm("fma.rn.f32x2 %0, %1, %2, %0;" : "+l"(d) : "l"(a), "l"(b));
}
__device__ __forceinline__ unsigned long long dup2(float v)
{
    unsigned long long r;
    unsigned u = __float_as_uint(v);
    asm("mov.b64 %0, {%1, %1};" : "=l"(r) : "r"(u));
    return r;
}
__device__ __forceinline__ float lo32(unsigned long long a)
{ return __uint_as_float((unsigned)a); }
__device__ __forceinline__ float hi32(unsigned long long a)
{ return __uint_as_float((unsigned)(a >> 32)); }

// ---------------- Kernel A: fused TMA fill + K-split f32x2 GEMM -------------
__global__ void __launch_bounds__(256) gemm_fill_kernel(
    const float* __restrict__ x, const float* __restrict__ wg,
    float* __restrict__ out, int out_size)
{
    __shared__ __align__(1024) float smbuf[FILL_CHUNK / 4];   // 32 KB union

    if (blockIdx.x < FILL_BLOCKS) {
        // ---- TMA bulk-store fill role ----
        float4* zb = (float4*)smbuf;
        for (int i = threadIdx.x; i < FILL_CHUNK / 16; i += 256)
            zb[i] = make_float4(0.f, 0.f, 0.f, 0.f);
        __syncthreads();
        asm volatile("fence.proxy.async.shared::cta;" ::: "memory");

        size_t   bytes = (size_t)out_size * sizeof(float);
        unsigned nch   = (unsigned)(bytes / FILL_CHUNK);
        uint32_t saddr = (uint32_t)__cvta_generic_to_shared(smbuf);

        if (threadIdx.x == 0) {
            for (unsigned c = blockIdx.x; c < nch; c += FILL_BLOCKS) {
                char* dst = (char*)out + (size_t)c * FILL_CHUNK;
                asm volatile(
                    "cp.async.bulk.global.shared::cta.bulk_group [%0], [%1], %2;"
                    :: "l"(dst), "r"(saddr), "r"((unsigned)FILL_CHUNK) : "memory");
            }
            asm volatile("cp.async.bulk.commit_group;" ::: "memory");
            asm volatile("cp.async.bulk.wait_group 0;" ::: "memory");
        }
        size_t tail = bytes % FILL_CHUNK;
        if (tail && blockIdx.x == 0) {
            char* p = (char*)out + bytes - tail;
            for (size_t i = threadIdx.x * 4; i + 3 < tail; i += 1024)
                *(float*)(p + i) = 0.f;
        }
        return;
    }

    // ---- GEMM role: 64 tokens x 64 experts, K-slice of 512 ----
    float* xsT = smbuf;              // [BK][XP] k-major, token minor
    float* wsT = smbuf + BK * XP;    // [BK][XP] k-major, expert minor

    int bid   = blockIdx.x - FILL_BLOCKS;
    int tid   = threadIdx.x;
    int kq    = bid & (KSPLIT - 1);
    int tok0  = (bid >> 2) * BT;
    int kbase = kq * KQ;

    int r = tid >> 2;                // 0..63: token row / expert row
    int c = tid & 3;                 // float4 column group

    const float* xptr = x  + (size_t)(tok0 + r) * D_DIM + kbase;
    const float* wptr = wg + (size_t)r          * D_DIM + kbase;

    unsigned long long acc[4][2];
#pragma unroll
    for (int i = 0; i < 4; i++) { acc[i][0] = 0ull; acc[i][1] = 0ull; }

    int txx = tid & 15;              // expert group: 4*txx
    int tyy = tid >> 4;              // token group:  4*tyy

    // preload tile 0
    float4 a0 = *(const float4*)(xptr + 4 * c);
    float4 a1 = *(const float4*)(xptr + 16 + 4 * c);
    float4 b0 = *(const float4*)(wptr + 4 * c);
    float4 b1 = *(const float4*)(wptr + 16 + 4 * c);

#pragma unroll 1
    for (int t = 0; t < KQ / BK; t++) {
        // store current tile transposed
        xsT[(4 * c + 0) * XP + r] = a0.x;
        xsT[(4 * c + 1) * XP + r] = a0.y;
        xsT[(4 * c + 2) * XP + r] = a0.z;
        xsT[(4 * c + 3) * XP + r] = a0.w;
        xsT[(4 * c + 16) * XP + r] = a1.x;
        xsT[(4 * c + 17) * XP + r] = a1.y;
        xsT[(4 * c + 18) * XP + r] = a1.z;
        xsT[(4 * c + 19) * XP + r] = a1.w;
        wsT[(4 * c + 0) * XP + r] = b0.x;
        wsT[(4 * c + 1) * XP + r] = b0.y;
        wsT[(4 * c + 2) * XP + r] = b0.z;
        wsT[(4 * c + 3) * XP + r] = b0.w;
        wsT[(4 * c + 16) * XP + r] = b1.x;
        wsT[(4 * c + 17) * XP + r] = b1.y;
        wsT[(4 * c + 18) * XP + r] = b1.z;
        wsT[(4 * c + 19) * XP + r] = b1.w;
        __syncthreads();

        // prefetch next tile into registers (latency hidden under compute)
        if (t + 1 < KQ / BK) {
            int off = (t + 1) * BK;
            a0 = *(const float4*)(xptr + off + 4 * c);
            a1 = *(const float4*)(xptr + off + 16 + 4 * c);
            b0 = *(const float4*)(wptr + off + 4 * c);
            b1 = *(const float4*)(wptr + off + 16 + 4 * c);
        }

        // compute: 32 kk x (4 tok x 4 exp) via packed f32x2
#pragma unroll
        for (int kk = 0; kk < BK; kk++) {
            float4 xv = *(const float4*)&xsT[kk * XP + 4 * tyy];
            ulonglong2 wp = *(const ulonglong2*)&wsT[kk * XP + 4 * txx];
            unsigned long long x0 = dup2(xv.x), x1 = dup2(xv.y);
            unsigned long long x2 = dup2(xv.z), x3 = dup2(xv.w);
            ffma2(acc[0][0], x0, wp.x); ffma2(acc[0][1], x0, wp.y);
            ffma2(acc[1][0], x1, wp.x); ffma2(acc[1][1], x1, wp.y);
            ffma2(acc[2][0], x2, wp.x); ffma2(acc[2][1], x2, wp.y);
            ffma2(acc[3][0], x3, wp.x); ffma2(acc[3][1], x3, wp.y);
        }
        __syncthreads();
    }

    // epilogue: write partial logits (coalesced float4)
#pragma unroll
    for (int i = 0; i < 4; i++) {
        *(float4*)&g_part[kq][tok0 + 4 * tyy + i][4 * txx] =
            make_float4(lo32(acc[i][0]), hi32(acc[i][0]),
                        lo32(acc[i][1]), hi32(acc[i][1]));
    }
}

// ---------------- Kernel B: sum 4 K-parts + top2 + softmax ------------------
__global__ void __launch_bounds__(256) top2_kernel()
{
    int t = blockIdx.x * 256 + threadIdx.x;    // token id

    const float4* p0 = (const float4*)&g_part[0][t][0];
    const float4* p1 = (const float4*)&g_part[1][t][0];
    const float4* p2 = (const float4*)&g_part[2][t][0];
    const float4* p3 = (const float4*)&g_part[3][t][0];

    float v0 = -3.4e38f, v1 = -3.4e38f;
    int e0 = 0, e1 = 0;
#pragma unroll
    for (int i = 0; i < N_EXP / 4; i++) {
        float4 a = p0[i], b = p1[i], cc = p2[i], d = p3[i];
        float s[4] = { ((a.x + b.x) + cc.x) + d.x,
                       ((a.y + b.y) + cc.y) + d.y,
                       ((a.z + b.z) + cc.z) + d.z,
                       ((a.w + b.w) + cc.w) + d.w };
#pragma unroll
        for (int j = 0; j < 4; j++) {
            float v = s[j];
            int   e = 4 * i + j;
            if (v > v0)      { v1 = v0; e1 = e0; v0 = v; e0 = e; }
            else if (v > v1) { v1 = v;  e1 = e; }
        }
    }
    float rr = expf(v1 - v0);
    float q0 = 1.f / (1.f + rr);
    float q1 = rr * q0;
    g_te[2 * t]     = e0;
    g_te[2 * t + 1] = e1;
    g_tw[2 * t]     = q0;
    g_tw[2 * t + 1] = q1;
}

// ---------------- Kernel C: order-exact capacity assignment -----------------
__global__ void __launch_bounds__(256) assign_kernel(float* __restrict__ out)
{
    int e    = blockIdx.x;            // expert 0..63
    int tid  = threadIdx.x;
    int lane = tid & 31;
    int wid  = tid >> 5;

    int ids[32];
    const int4* te4 = (const int4*)g_te;
#pragma unroll
    for (int k = 0; k < 8; k++) {
        int4 v = te4[tid * 8 + k];
        ids[4 * k + 0] = v.x; ids[4 * k + 1] = v.y;
        ids[4 * k + 2] = v.z; ids[4 * k + 3] = v.w;
    }

    int cnt = 0;
#pragma unroll
    for (int k = 0; k < 32; k++) cnt += (ids[k] == e);

    int c = cnt;
#pragma unroll
    for (int o = 1; o < 32; o <<= 1) {
        int n = __shfl_up_sync(0xffffffffu, c, o);
        if (lane >= o) c += n;
    }
    __shared__ int wsum[8];
    if (lane == 31) wsum[wid] = c;
    __syncthreads();
    if (wid == 0 && lane < 8) {
        int v = wsum[lane];
#pragma unroll
        for (int o = 1; o < 8; o <<= 1) {
            int n = __shfl_up_sync(0xffu, v, o);
            if (lane >= o) v += n;
        }
        wsum[lane] = v;
    }
    __syncthreads();
    int prefix = c - cnt + (wid ? wsum[wid - 1] : 0);
    int total  = wsum[7];

    float* cb = out + N_EXP;
    float* mk = out + N_EXP + TEC;
    int slot = prefix;
#pragma unroll
    for (int k = 0; k < 32; k++) {
        if (ids[k] == e) {
            if (slot < CAP) {
                int a = tid * 32 + k;
                int t = a >> 1;
                size_t idx = (size_t)t * (N_EXP * CAP) + (size_t)e * CAP + slot;
                cb[idx] = g_tw[a];
                mk[idx] = 1.0f;
            }
            slot++;
        }
    }

    if (tid == 0)
        out[e] = (float)(total < CAP ? total : CAP);
}

extern "C" void kernel_launch(void* const* d_in, const int* in_sizes, int n_in,
                              void* d_out, int out_size)
{
    const float* x  = (const float*)d_in[0];
    const float* wg = (const float*)d_in[1];
    float* out = (float*)d_out;

    gemm_fill_kernel<<<FILL_BLOCKS + GEMM_BLOCKS, 256>>>(x, wg, out, out_size);
    top2_kernel<<<T_TOK / 256, 256>>>();
    assign_kernel<<<N_EXP, 256>>>(out);
}